// round 13
// baseline (speedup 1.0000x reference)
#include <cuda_runtime.h>
#include <cstdint>
#include <cstddef>

typedef long long ll;

#define BB 4
#define NN 1024
#define DD 512
#define HH 8
#define LL 12
#define NP1 1025
#define CPS (NP1*NP1)
#define XSZ ((size_t)BB*NN*DD)
#define NORMC  (-7.6246189861593985f)
#define LOGNC  (6.9314718055994531f)

// ---------------- static scratch pool ----------------
constexpr size_t O_X   = 0;                                  // [2][4096][512]
constexpr size_t O_Q   = O_X   + 2*XSZ;
constexpr size_t O_K   = O_Q   + 2*XSZ;
constexpr size_t O_V   = O_K   + 2*XSZ;
constexpr size_t O_S   = O_V   + 2*XSZ;                      // [4][8][1024][1024]
constexpr size_t O_AO  = O_S   + (size_t)BB*HH*NN*NN;
constexpr size_t O_CAT = O_AO  + 2*XSZ;                      // [8192][1024]
constexpr size_t O_Z   = O_CAT + (size_t)2*BB*NN*2*DD;
constexpr size_t O_MEAN= O_Z   + (size_t)2*BB*NN*2*DD;
constexpr size_t O_RSTD= O_MEAN+ (size_t)2*BB*2*DD;
constexpr size_t O_WMP = O_RSTD+ (size_t)2*BB*2*DD;
constexpr size_t O_CP  = O_WMP + (size_t)LL*DD*DD;
constexpr size_t O_ER  = O_CP  + (size_t)BB*CPS;
constexpr size_t O_EC  = O_ER  + (size_t)BB*CPS;
constexpr size_t O_RM  = O_EC  + (size_t)BB*CPS;
constexpr size_t O_CM  = O_RM  + (size_t)BB*NP1;
constexpr size_t O_U   = O_CM  + (size_t)BB*NP1;
constexpr size_t O_VV  = O_U   + (size_t)BB*NP1;
constexpr size_t O_EU  = O_VV  + (size_t)BB*NP1;
constexpr size_t O_EV  = O_EU  + (size_t)BB*NP1;
constexpr size_t POOLN = O_EV  + (size_t)BB*NP1;
__device__ float g_pool[POOLN];

// ---------------- block reductions ----------------
__device__ __forceinline__ float bsum256(float v, float* sh) {
    int t = threadIdx.x; sh[t] = v; __syncthreads();
#pragma unroll
    for (int s = 128; s > 0; s >>= 1) { if (t < s) sh[t] += sh[t+s]; __syncthreads(); }
    float r = sh[0]; __syncthreads(); return r;
}
__device__ __forceinline__ float bmax256(float v, float* sh) {
    int t = threadIdx.x; sh[t] = v; __syncthreads();
#pragma unroll
    for (int s = 128; s > 0; s >>= 1) { if (t < s) sh[t] = fmaxf(sh[t], sh[t+s]); __syncthreads(); }
    float r = sh[0]; __syncthreads(); return r;
}

// ---------------- GEMM ----------------
// C[m,n] = alpha * sum_k A[m,k]*B(n,k or k,n) (+bias[n]) (+Res[m,n])
// Batched over blockIdx.z: zb=z/NH, zh=z%NH with per-axis strides.
template<int BM,int BN,int BK,int TM,int TN,bool BT>
__global__ __launch_bounds__((BM/TM)*(BN/TN))
void gemm_k(const float* __restrict__ A, const float* __restrict__ B,
            const float* __restrict__ bias, const float* __restrict__ Res,
            float* __restrict__ C,
            int M, int N, int K, int lda, int ldb, int ldc,
            int NH, ll sAb, ll sAh, ll sBb, ll sBh, ll sCb, ll sCh, float alpha)
{
    constexpr int THREADS = (BM/TM)*(BN/TN);
    __shared__ float As[BK][BM+4];
    __shared__ float Bs[BK][BN];
    int z = blockIdx.z, zb = z / NH, zh = z % NH;
    A += zb*sAb + zh*sAh;
    B += zb*sBb + zh*sBh;
    C += zb*sCb + zh*sCh;
    const float* R = Res ? (Res + zb*sCb + zh*sCh) : nullptr;
    const int tid = threadIdx.x;
    const int m0 = blockIdx.y * BM, n0 = blockIdx.x * BN;
    const int tr = tid / (BN/TN), tc = tid % (BN/TN);
    float acc[TM][TN] = {};
    for (int k0 = 0; k0 < K; k0 += BK) {
#pragma unroll
        for (int it = 0; it < BM*BK/THREADS; it++) {
            int i = tid + it*THREADS;
            int m = i / BK, kk = i % BK;
            As[kk][m] = A[(size_t)(m0+m)*lda + (k0+kk)];
        }
        if constexpr (BT) {
#pragma unroll
            for (int it = 0; it < BN*BK/THREADS; it++) {
                int i = tid + it*THREADS;
                int n = i / BK, kk = i % BK;
                Bs[kk][n] = B[(size_t)(n0+n)*ldb + (k0+kk)];
            }
        } else {
#pragma unroll
            for (int it = 0; it < BN*BK/THREADS; it++) {
                int i = tid + it*THREADS;
                int kk = i / BN, n = i % BN;
                Bs[kk][n] = B[(size_t)(k0+kk)*ldb + (n0+n)];
            }
        }
        __syncthreads();
#pragma unroll
        for (int kk = 0; kk < BK; kk++) {
            float4 a0 = *reinterpret_cast<const float4*>(&As[kk][tr*TM]);
            float4 a1 = *reinterpret_cast<const float4*>(&As[kk][tr*TM+4]);
            float ar[8] = {a0.x,a0.y,a0.z,a0.w,a1.x,a1.y,a1.z,a1.w};
            float br[TN];
            if constexpr (TN == 8) {
                float4 b0 = *reinterpret_cast<const float4*>(&Bs[kk][tc*4]);
                float4 b1 = *reinterpret_cast<const float4*>(&Bs[kk][BN/2 + tc*4]);
                br[0]=b0.x; br[1]=b0.y; br[2]=b0.z; br[3]=b0.w;
                br[4]=b1.x; br[5]=b1.y; br[6]=b1.z; br[7]=b1.w;
            } else {
                float4 b0 = *reinterpret_cast<const float4*>(&Bs[kk][tc*TN]);
                br[0]=b0.x; br[1]=b0.y; br[2]=b0.z; br[3]=b0.w;
            }
#pragma unroll
            for (int i = 0; i < TM; i++)
#pragma unroll
                for (int j = 0; j < TN; j++)
                    acc[i][j] += ar[i]*br[j];
        }
        __syncthreads();
    }
#pragma unroll
    for (int i = 0; i < TM; i++) {
        int m = m0 + tr*TM + i;
#pragma unroll
        for (int j = 0; j < TN; j++) {
            int n;
            if constexpr (TN == 8) n = n0 + ((j < 4) ? (tc*4 + j) : (BN/2 + tc*4 + (j-4)));
            else                   n = n0 + tc*TN + j;
            float v = acc[i][j]*alpha;
            if (bias) v += bias[n];
            if (R)    v += R[(size_t)m*ldc + n];
            C[(size_t)m*ldc + n] = v;
        }
    }
}

// ---------------- small kernels ----------------
__global__ void perm_k(const float* __restrict__ Wm, float* __restrict__ Wp) {
    int i = blockIdx.x*256 + threadIdx.x;
    if (i >= LL*DD*DD) return;
    int r = i % (DD*DD);
    int c = r % DD;
    int h = c / 64, hd = c % 64;
    // Wp[l][o][h*64+hd] = Wm[l][o][hd*8+h]
    Wp[i] = Wm[(size_t)(i - c) + hd*HH + h];
}

__global__ void softmax_k(float* __restrict__ S) {
    float4* p = reinterpret_cast<float4*>(S + (size_t)blockIdx.x*NN);
    float4 v = p[threadIdx.x];
    __shared__ float sh[256];
    float m = fmaxf(fmaxf(v.x, v.y), fmaxf(v.z, v.w));
    m = bmax256(m, sh);
    v.x = __expf(v.x-m); v.y = __expf(v.y-m); v.z = __expf(v.z-m); v.w = __expf(v.w-m);
    float s = bsum256(v.x+v.y+v.z+v.w, sh);
    float inv = 1.f/s;
    v.x *= inv; v.y *= inv; v.z *= inv; v.w *= inv;
    p[threadIdx.x] = v;
}

__global__ void cat_copy_k(const float* __restrict__ x, float* __restrict__ cat) {
    size_t i = (size_t)blockIdx.x*256 + threadIdx.x;
    if (i >= 2*XSZ) return;
    size_t bn = i >> 9;
    int c = (int)(i & 511);
    cat[bn*1024 + c] = x[i];
}

__global__ void in_stats_k(const float* __restrict__ z, float* __restrict__ mean,
                           float* __restrict__ rstd) {
    int c = blockIdx.x*32 + (threadIdx.x & 31);
    int gb = blockIdx.y;
    int rl = threadIdx.x >> 5;
    const float* p = z + (size_t)gb*NN*1024 + c;
    float s = 0.f, s2 = 0.f;
    for (int n = rl; n < NN; n += 8) {
        float v = p[(size_t)n*1024];
        s += v; s2 += v*v;
    }
    __shared__ float sa[256], sb[256];
    sa[threadIdx.x] = s; sb[threadIdx.x] = s2; __syncthreads();
#pragma unroll
    for (int off = 128; off >= 32; off >>= 1) {
        if (threadIdx.x < off) { sa[threadIdx.x] += sa[threadIdx.x+off]; sb[threadIdx.x] += sb[threadIdx.x+off]; }
        __syncthreads();
    }
    if (threadIdx.x < 32) {
        float m = sa[threadIdx.x] * (1.f/NN);
        float var = sb[threadIdx.x] * (1.f/NN) - m*m;
        mean[gb*1024 + c] = m;
        rstd[gb*1024 + c] = rsqrtf(var + 1e-5f);
    }
}

__global__ void in_apply_k(float* __restrict__ z, const float* __restrict__ mean,
                           const float* __restrict__ rstd) {
    size_t i = (size_t)blockIdx.x*256 + threadIdx.x;
    if (i >= (size_t)2*BB*NN*1024) return;
    int c  = (int)(i & 1023);
    int gb = (int)(i >> 20);
    float v = (z[i] - mean[gb*1024 + c]) * rstd[gb*1024 + c];
    z[i] = fmaxf(v, 0.f);
}

__global__ void bins_k(float* __restrict__ cp, const float* __restrict__ alpha_p) {
    int i = blockIdx.x*256 + threadIdx.x;
    if (i >= BB*NP1) return;
    float a = *alpha_p;
    int b = i / NP1, r = i % NP1;
    float* base = cp + (size_t)b*CPS;
    base[(size_t)r*NP1 + 1024] = a;
    base[(size_t)1024*NP1 + r] = a;
}

__global__ void erow_k(const float* __restrict__ cp, float* __restrict__ er,
                       float* __restrict__ rm) {
    int i = blockIdx.x, b = blockIdx.y;
    const float* row = cp + (size_t)b*CPS + (size_t)i*NP1;
    float m = -1e30f;
    for (int j = threadIdx.x; j < NP1; j += 256) m = fmaxf(m, row[j]);
    __shared__ float sh[256];
    m = bmax256(m, sh);
    float* e = er + (size_t)b*CPS + (size_t)i*NP1;
    for (int j = threadIdx.x; j < NP1; j += 256) e[j] = __expf(row[j] - m);
    if (threadIdx.x == 0) rm[b*NP1 + i] = m;
}

__global__ void cmax_k(const float* __restrict__ cp, float* __restrict__ cm) {
    int j = blockIdx.x*256 + threadIdx.x, b = blockIdx.y;
    if (j >= NP1) return;
    const float* base = cp + (size_t)b*CPS + j;
    float m = -1e30f;
    for (int i = 0; i < NP1; i++) m = fmaxf(m, base[(size_t)i*NP1]);
    cm[b*NP1 + j] = m;
}

__global__ void texp_k(const float* __restrict__ cp, const float* __restrict__ cm,
                       float* __restrict__ ect) {
    __shared__ float t[32][33];
    int b = blockIdx.z;
    int i0 = blockIdx.y*32, j0 = blockIdx.x*32;
    int i = i0 + threadIdx.y, j = j0 + threadIdx.x;
    if (i < NP1 && j < NP1)
        t[threadIdx.y][threadIdx.x] = cp[(size_t)b*CPS + (size_t)i*NP1 + j];
    __syncthreads();
    int jo = j0 + threadIdx.y, io = i0 + threadIdx.x;
    if (jo < NP1 && io < NP1)
        ect[(size_t)b*CPS + (size_t)jo*NP1 + io] = __expf(t[threadIdx.x][threadIdx.y] - cm[b*NP1 + jo]);
}

__global__ void initev_k(float* __restrict__ ev) {
    int i = blockIdx.x*256 + threadIdx.x;
    if (i < BB*NP1) ev[i] = 1.f;
}

__global__ void iter_k(const float* __restrict__ E, const float* __restrict__ evin,
                       const float* __restrict__ mx, float* __restrict__ lg,
                       float* __restrict__ ex) {
    int i = blockIdx.x, b = blockIdx.y;
    const float* row = E + (size_t)b*CPS + (size_t)i*NP1;
    const float* ev = evin + b*NP1;
    float s = 0.f;
    for (int j = threadIdx.x; j < NP1; j += 256) s += row[j]*ev[j];
    __shared__ float sh[256];
    s = bsum256(s, sh);
    if (threadIdx.x == 0) {
        float lmu = (i < NN) ? NORMC : (LOGNC + NORMC);
        float o = lmu - (mx[b*NP1 + i] + logf(s));
        lg[b*NP1 + i] = o;
        ex[b*NP1 + i] = expf(o);
    }
}

__global__ void out_k(const float* __restrict__ cp, const float* __restrict__ u,
                      const float* __restrict__ v, float* __restrict__ out) {
    size_t idx = (size_t)blockIdx.x*256 + threadIdx.x;
    if (idx >= (size_t)BB*CPS) return;
    int b = (int)(idx / CPS);
    int r = (int)(idx % CPS);
    int i = r / NP1, j = r % NP1;
    out[idx] = cp[idx] + u[b*NP1 + i] + v[b*NP1 + j] - NORMC;
}

// ---------------- host wrappers ----------------
static void GT(const float* A, const float* B, const float* bias, const float* Res,
               float* C, int M, int N, int K, int lda, int ldb, int ldc,
               int nz, int NH, ll sAb, ll sAh, ll sBb, ll sBh, ll sCb, ll sCh,
               float alpha) {
    dim3 g(N/128, M/128, nz);
    gemm_k<128,128,8,8,8,true><<<g,256>>>(A,B,bias,Res,C,M,N,K,lda,ldb,ldc,
                                          NH,sAb,sAh,sBb,sBh,sCb,sCh,alpha);
}
static void GNF(const float* A, const float* B, float* C, int M, int N, int K,
                int lda, int ldb, int ldc, int nz, int NH,
                ll sAb, ll sAh, ll sBb, ll sBh, ll sCb, ll sCh) {
    dim3 g(N/64, M/128, nz);
    gemm_k<128,64,8,8,4,false><<<g,256>>>(A,B,nullptr,nullptr,C,M,N,K,lda,ldb,ldc,
                                          NH,sAb,sAh,sBb,sBh,sCb,sCh,1.f);
}

extern "C" void kernel_launch(void* const* d_in, const int* in_sizes, int n_in,
                              void* d_out, int out_size) {
    (void)in_sizes; (void)n_in; (void)out_size;
    float* P = nullptr;
    cudaGetSymbolAddress((void**)&P, g_pool);

    const float* descs0 = (const float*)d_in[0];
    const float* descs1 = (const float*)d_in[1];
    const float* Wq = (const float*)d_in[2];  const float* bq = (const float*)d_in[3];
    const float* Wk = (const float*)d_in[4];  const float* bk = (const float*)d_in[5];
    const float* Wv = (const float*)d_in[6];  const float* bv = (const float*)d_in[7];
    const float* Wm = (const float*)d_in[8];  const float* bm = (const float*)d_in[9];
    const float* W1 = (const float*)d_in[10]; const float* b1 = (const float*)d_in[11];
    const float* W2 = (const float*)d_in[12]; const float* b2 = (const float*)d_in[13];
    const float* Wf = (const float*)d_in[14]; const float* bf = (const float*)d_in[15];
    const float* bscore = (const float*)d_in[16];
    float* out = (float*)d_out;

    float* X   = P + O_X;
    float* Qb  = P + O_Q;
    float* Kb  = P + O_K;
    float* Vb  = P + O_V;
    float* Sb  = P + O_S;
    float* AO  = P + O_AO;
    float* CAT = P + O_CAT;
    float* Zb  = P + O_Z;
    float* MEAN= P + O_MEAN;
    float* RSTD= P + O_RSTD;
    float* WMP = P + O_WMP;
    float* CP  = P + O_CP;
    float* ER  = P + O_ER;
    float* EC  = P + O_EC;
    float* RM  = P + O_RM;
    float* CM  = P + O_CM;
    float* U   = P + O_U;
    float* VV  = P + O_VV;
    float* EU  = P + O_EU;
    float* EV  = P + O_EV;

    // init: x0|x1 node-major (inputs are already [B,N,D])
    cudaMemcpyAsync(X,        descs0, XSZ*sizeof(float), cudaMemcpyDeviceToDevice);
    cudaMemcpyAsync(X + XSZ,  descs1, XSZ*sizeof(float), cudaMemcpyDeviceToDevice);
    perm_k<<<(LL*DD*DD+255)/256, 256>>>(Wm, WMP);

    const ll sBN = (ll)NN*DD;   // per-batch stride in Q/K/V/X (node-major)
    for (int l = 0; l < LL; l++) {
        bool cross = (l & 1);
        const float* wq = Wq + (size_t)l*DD*DD;
        const float* wk = Wk + (size_t)l*DD*DD;
        const float* wv = Wv + (size_t)l*DD*DD;
        const float* wmp= WMP+ (size_t)l*DD*DD;
        const float* w1 = W1 + (size_t)l*2*DD*2*DD;
        const float* w2 = W2 + (size_t)l*DD*2*DD;

        // projections for BOTH graphs from pre-update X
        GT(X, wq, bq + l*DD, nullptr, Qb, 8192, 512, 512, 512,512,512, 1,1, 0,0,0,0,0,0, 1.f);
        GT(X, wk, bk + l*DD, nullptr, Kb, 8192, 512, 512, 512,512,512, 1,1, 0,0,0,0,0,0, 1.f);
        GT(X, wv, bv + l*DD, nullptr, Vb, 8192, 512, 512, 512,512,512, 1,1, 0,0,0,0,0,0, 1.f);

        for (int g = 0; g < 2; g++) {
            int sg = cross ? 1-g : g;
            const float* Qg = Qb + (size_t)g*XSZ;
            const float* Kg = Kb + (size_t)sg*XSZ;
            const float* Vg = Vb + (size_t)sg*XSZ;
            // scores[b,h,n,m] = Q·K / 8
            GT(Qg, Kg, nullptr, nullptr, Sb, 1024,1024,64, 512,512,1024,
               BB*HH, HH, sBN, 64, sBN, 64, (ll)HH*NN*NN, (ll)NN*NN, 0.125f);
            softmax_k<<<BB*HH*NN, 256>>>(Sb);
            // AO[b,n,h*64+hd] = P·V
            GNF(Sb, Vg, AO + (size_t)g*XSZ, 1024,64,1024, 1024,512,512,
                BB*HH, HH, (ll)HH*NN*NN, (ll)NN*NN, sBN, 64, sBN, 64);
        }
        // msg into CAT[:,512:1024]
        GT(AO, wmp, bm + l*DD, nullptr, CAT + 512, 8192,512,512, 512,512,1024,
           1,1, 0,0,0,0,0,0, 1.f);
        cat_copy_k<<<(int)((2*XSZ+255)/256), 256>>>(X, CAT);
        // z = CAT @ W1^T + b1
        GT(CAT, w1, b1 + l*2*DD, nullptr, Zb, 8192,1024,1024, 1024,1024,1024,
           1,1, 0,0,0,0,0,0, 1.f);
        in_stats_k<<<dim3(32, 8), 256>>>(Zb, MEAN, RSTD);
        in_apply_k<<<(int)(((size_t)2*BB*NN*1024 + 255)/256), 256>>>(Zb, MEAN, RSTD);
        // X += Z @ W2^T + b2
        GT(Zb, w2, b2 + l*DD, X, X, 8192,512,1024, 1024,1024,512,
           1,1, 0,0,0,0,0,0, 1.f);
    }

    // final projection (m0|m1 into Qb)
    GT(X, Wf, bf, nullptr, Qb, 8192,512,512, 512,512,512, 1,1, 0,0,0,0,0,0, 1.f);
    // scores -> couplings interior (ldc = 1025)
    GT(Qb, Qb + XSZ, nullptr, nullptr, CP, 1024,1024,512, 512,512,NP1,
       BB, 1, sBN, 0, sBN, 0, (ll)CPS, 0, 0.044194173824159216f);
    bins_k<<<(BB*NP1+255)/256, 256>>>(CP, bscore);

    // Sinkhorn: precompute stabilized exponentials once
    erow_k<<<dim3(NP1, BB), 256>>>(CP, ER, RM);
    cmax_k<<<dim3((NP1+255)/256, BB), 256>>>(CP, CM);
    texp_k<<<dim3(33, 33, BB), dim3(32, 32)>>>(CP, CM, EC);
    initev_k<<<(BB*NP1+255)/256, 256>>>(EV);
    for (int it = 0; it < 100; it++) {
        iter_k<<<dim3(NP1, BB), 256>>>(ER, EV, RM, U, EU);   // u-update
        iter_k<<<dim3(NP1, BB), 256>>>(EC, EU, CM, VV, EV);  // v-update
    }
    out_k<<<(int)(((size_t)BB*CPS + 255)/256), 256>>>(CP, U, VV, out);
}

// round 15
// speedup vs baseline: 1.0699x; 1.0699x over previous
#include <cuda_runtime.h>
#include <cstdint>
#include <cstddef>

typedef long long ll;

#define BB 4
#define NN 1024
#define DD 512
#define HH 8
#define LL 12
#define NP1 1025
#define CPS (NP1*NP1)
#define XSZ ((size_t)BB*NN*DD)
#define NORMC  (-7.6246189861593985f)
#define LOGNC  (6.9314718055994531f)

// ---------------- static scratch pool ----------------
constexpr size_t O_X   = 0;                                  // [2][4096][512]
constexpr size_t O_Q   = O_X   + 2*XSZ;
constexpr size_t O_K   = O_Q   + 2*XSZ;
constexpr size_t O_V   = O_K   + 2*XSZ;
constexpr size_t O_S   = O_V   + 2*XSZ;                      // [4][8][1024][1024]
constexpr size_t O_AO  = O_S   + (size_t)BB*HH*NN*NN;
constexpr size_t O_CAT = O_AO  + 2*XSZ;                      // [8192][1024]
constexpr size_t O_Z   = O_CAT + (size_t)2*BB*NN*2*DD;
constexpr size_t O_MEAN= O_Z   + (size_t)2*BB*NN*2*DD;
constexpr size_t O_RSTD= O_MEAN+ (size_t)2*BB*2*DD;
constexpr size_t O_WMP = O_RSTD+ (size_t)2*BB*2*DD;
constexpr size_t O_CP  = O_WMP + (size_t)LL*DD*DD;
constexpr size_t O_ER  = O_CP  + (size_t)BB*CPS;
constexpr size_t O_EC  = O_ER  + (size_t)BB*CPS;
constexpr size_t O_RM  = O_EC  + (size_t)BB*CPS;
constexpr size_t O_CM  = O_RM  + (size_t)BB*NP1;
constexpr size_t O_U   = O_CM  + (size_t)BB*NP1;
constexpr size_t O_VV  = O_U   + (size_t)BB*NP1;
constexpr size_t O_EU  = O_VV  + (size_t)BB*NP1;
constexpr size_t O_EV  = O_EU  + (size_t)BB*NP1;
constexpr size_t POOLN = O_EV  + (size_t)BB*NP1;
__device__ float g_pool[POOLN];

// ---------------- f32x2 helpers ----------------
__device__ __forceinline__ uint64_t pk2(float x, float y) {
    uint64_t r; asm("mov.b64 %0, {%1, %2};" : "=l"(r) : "f"(x), "f"(y)); return r;
}
__device__ __forceinline__ void upk2(uint64_t v, float& x, float& y) {
    asm("mov.b64 {%0, %1}, %2;" : "=f"(x), "=f"(y) : "l"(v));
}
__device__ __forceinline__ void fma2(uint64_t& d, uint64_t a, uint64_t b) {
    asm("fma.rn.f32x2 %0, %1, %2, %3;" : "=l"(d) : "l"(a), "l"(b), "l"(d));
}

// ---------------- block reductions ----------------
__device__ __forceinline__ float bsum256(float v, float* sh) {
    int t = threadIdx.x; sh[t] = v; __syncthreads();
#pragma unroll
    for (int s = 128; s > 0; s >>= 1) { if (t < s) sh[t] += sh[t+s]; __syncthreads(); }
    float r = sh[0]; __syncthreads(); return r;
}
__device__ __forceinline__ float bmax256(float v, float* sh) {
    int t = threadIdx.x; sh[t] = v; __syncthreads();
#pragma unroll
    for (int s = 128; s > 0; s >>= 1) { if (t < s) sh[t] = fmaxf(sh[t], sh[t+s]); __syncthreads(); }
    float r = sh[0]; __syncthreads(); return r;
}

// ---------------- GEMM (fp32 via packed f32x2 FMA) ----------------
// C[m,n] = alpha * sum_k A[m,k]*B(n,k or k,n) (+bias[n]) (+Res[m,n])
// Batched over blockIdx.z: zb=z/NH, zh=z%NH with per-axis strides.
template<int BM,int BN,int BK,int TM,int TN,bool BT>
__global__ __launch_bounds__((BM/TM)*(BN/TN), 2)
void gemm_k(const float* __restrict__ A, const float* __restrict__ B,
            const float* __restrict__ bias, const float* __restrict__ Res,
            float* __restrict__ C,
            int M, int N, int K, int lda, int ldb, int ldc,
            int NH, ll sAb, ll sAh, ll sBb, ll sBh, ll sCb, ll sCh, float alpha)
{
    constexpr int THREADS = (BM/TM)*(BN/TN);
    constexpr int TN2 = TN/2;
    constexpr int APT = BM*BK/THREADS;
    constexpr int BPT = BN*BK/THREADS;
    __shared__ float As[BK][BM+4];
    __shared__ float Bs[BK][BN+4];
    int z = blockIdx.z, zb = z / NH, zh = z % NH;
    A += zb*sAb + zh*sAh;
    B += zb*sBb + zh*sBh;
    C += zb*sCb + zh*sCh;
    const float* R = Res ? (Res + zb*sCb + zh*sCh) : nullptr;
    const int tid = threadIdx.x;
    const int m0 = blockIdx.y * BM, n0 = blockIdx.x * BN;
    const int tr = tid / (BN/TN), tc = tid % (BN/TN);

    uint64_t acc[TM][TN2];
#pragma unroll
    for (int i = 0; i < TM; i++)
#pragma unroll
        for (int j = 0; j < TN2; j++) acc[i][j] = 0ull;

    float pa[APT], pb[BPT];
    // prefetch tile 0
#pragma unroll
    for (int it = 0; it < APT; it++) {
        int i = tid + it*THREADS;
        int m = i / BK, kk = i % BK;
        pa[it] = A[(size_t)(m0+m)*lda + kk];
    }
    if constexpr (BT) {
#pragma unroll
        for (int it = 0; it < BPT; it++) {
            int i = tid + it*THREADS;
            int n = i / BK, kk = i % BK;
            pb[it] = B[(size_t)(n0+n)*ldb + kk];
        }
    } else {
#pragma unroll
        for (int it = 0; it < BPT; it++) {
            int i = tid + it*THREADS;
            int kk = i / BN, n = i % BN;
            pb[it] = B[(size_t)kk*ldb + (n0+n)];
        }
    }

    const int nsteps = K / BK;
    for (int s = 0; s < nsteps; s++) {
        // store staged tile to smem
#pragma unroll
        for (int it = 0; it < APT; it++) {
            int i = tid + it*THREADS;
            int m = i / BK, kk = i % BK;
            As[kk][m] = pa[it];
        }
        if constexpr (BT) {
#pragma unroll
            for (int it = 0; it < BPT; it++) {
                int i = tid + it*THREADS;
                int n = i / BK, kk = i % BK;
                Bs[kk][n] = pb[it];
            }
        } else {
#pragma unroll
            for (int it = 0; it < BPT; it++) {
                int i = tid + it*THREADS;
                int kk = i / BN, n = i % BN;
                Bs[kk][n] = pb[it];
            }
        }
        __syncthreads();
        // prefetch next tile (overlaps with compute)
        if (s + 1 < nsteps) {
            int k0 = (s+1)*BK;
#pragma unroll
            for (int it = 0; it < APT; it++) {
                int i = tid + it*THREADS;
                int m = i / BK, kk = i % BK;
                pa[it] = A[(size_t)(m0+m)*lda + (k0+kk)];
            }
            if constexpr (BT) {
#pragma unroll
                for (int it = 0; it < BPT; it++) {
                    int i = tid + it*THREADS;
                    int n = i / BK, kk = i % BK;
                    pb[it] = B[(size_t)(n0+n)*ldb + (k0+kk)];
                }
            } else {
#pragma unroll
                for (int it = 0; it < BPT; it++) {
                    int i = tid + it*THREADS;
                    int kk = i / BN, n = i % BN;
                    pb[it] = B[(size_t)(k0+kk)*ldb + (n0+n)];
                }
            }
        }
        // compute
#pragma unroll
        for (int kk = 0; kk < BK; kk++) {
            float4 a0 = *reinterpret_cast<const float4*>(&As[kk][tr*TM]);
            float4 a1 = *reinterpret_cast<const float4*>(&As[kk][tr*TM+4]);
            uint64_t ad[TM];
            ad[0]=pk2(a0.x,a0.x); ad[1]=pk2(a0.y,a0.y); ad[2]=pk2(a0.z,a0.z); ad[3]=pk2(a0.w,a0.w);
            ad[4]=pk2(a1.x,a1.x); ad[5]=pk2(a1.y,a1.y); ad[6]=pk2(a1.z,a1.z); ad[7]=pk2(a1.w,a1.w);
            uint64_t bd[TN2];
            if constexpr (TN == 8) {
                float4 b0 = *reinterpret_cast<const float4*>(&Bs[kk][tc*4]);
                float4 b1 = *reinterpret_cast<const float4*>(&Bs[kk][BN/2 + tc*4]);
                bd[0]=pk2(b0.x,b0.y); bd[1]=pk2(b0.z,b0.w);
                bd[2]=pk2(b1.x,b1.y); bd[3]=pk2(b1.z,b1.w);
            } else {
                float4 b0 = *reinterpret_cast<const float4*>(&Bs[kk][tc*TN]);
                bd[0]=pk2(b0.x,b0.y); bd[1]=pk2(b0.z,b0.w);
            }
#pragma unroll
            for (int i = 0; i < TM; i++)
#pragma unroll
                for (int j = 0; j < TN2; j++)
                    fma2(acc[i][j], ad[i], bd[j]);
        }
        __syncthreads();
    }
#pragma unroll
    for (int i = 0; i < TM; i++) {
        int m = m0 + tr*TM + i;
#pragma unroll
        for (int j = 0; j < TN2; j++) {
            float lo, hi;
            upk2(acc[i][j], lo, hi);
            int n;
            if constexpr (TN == 8) n = (j < 2) ? (n0 + tc*4 + 2*j) : (n0 + BN/2 + tc*4 + 2*(j-2));
            else                   n = n0 + tc*TN + 2*j;
            float v0 = lo*alpha, v1 = hi*alpha;
            if (bias) { v0 += bias[n]; v1 += bias[n+1]; }
            if (R)    { v0 += R[(size_t)m*ldc + n]; v1 += R[(size_t)m*ldc + n + 1]; }
            C[(size_t)m*ldc + n]     = v0;
            C[(size_t)m*ldc + n + 1] = v1;
        }
    }
}

// ---------------- small kernels ----------------
__global__ void perm_k(const float* __restrict__ Wm, float* __restrict__ Wp) {
    int i = blockIdx.x*256 + threadIdx.x;
    if (i >= LL*DD*DD) return;
    int r = i % (DD*DD);
    int c = r % DD;
    int h = c / 64, hd = c % 64;
    Wp[i] = Wm[(size_t)(i - c) + hd*HH + h];
}

__global__ void softmax_k(float* __restrict__ S) {
    float4* p = reinterpret_cast<float4*>(S + (size_t)blockIdx.x*NN);
    float4 v = p[threadIdx.x];
    __shared__ float sh[256];
    float m = fmaxf(fmaxf(v.x, v.y), fmaxf(v.z, v.w));
    m = bmax256(m, sh);
    v.x = __expf(v.x-m); v.y = __expf(v.y-m); v.z = __expf(v.z-m); v.w = __expf(v.w-m);
    float s = bsum256(v.x+v.y+v.z+v.w, sh);
    float inv = 1.f/s;
    v.x *= inv; v.y *= inv; v.z *= inv; v.w *= inv;
    p[threadIdx.x] = v;
}

__global__ void cat_copy_k(const float* __restrict__ x, float* __restrict__ cat) {
    size_t i = (size_t)blockIdx.x*256 + threadIdx.x;
    if (i >= 2*XSZ) return;
    size_t bn = i >> 9;
    int c = (int)(i & 511);
    cat[bn*1024 + c] = x[i];
}

__global__ void in_stats_k(const float* __restrict__ z, float* __restrict__ mean,
                           float* __restrict__ rstd) {
    int c = blockIdx.x*32 + (threadIdx.x & 31);
    int gb = blockIdx.y;
    int rl = threadIdx.x >> 5;
    const float* p = z + (size_t)gb*NN*1024 + c;
    float s = 0.f, s2 = 0.f;
    for (int n = rl; n < NN; n += 8) {
        float v = p[(size_t)n*1024];
        s += v; s2 += v*v;
    }
    __shared__ float sa[256], sb[256];
    sa[threadIdx.x] = s; sb[threadIdx.x] = s2; __syncthreads();
#pragma unroll
    for (int off = 128; off >= 32; off >>= 1) {
        if (threadIdx.x < off) { sa[threadIdx.x] += sa[threadIdx.x+off]; sb[threadIdx.x] += sb[threadIdx.x+off]; }
        __syncthreads();
    }
    if (threadIdx.x < 32) {
        float m = sa[threadIdx.x] * (1.f/NN);
        float var = sb[threadIdx.x] * (1.f/NN) - m*m;
        mean[gb*1024 + c] = m;
        rstd[gb*1024 + c] = rsqrtf(var + 1e-5f);
    }
}

__global__ void in_apply_k(float* __restrict__ z, const float* __restrict__ mean,
                           const float* __restrict__ rstd) {
    size_t i = (size_t)blockIdx.x*256 + threadIdx.x;
    if (i >= (size_t)2*BB*NN*1024) return;
    int c  = (int)(i & 1023);
    int gb = (int)(i >> 20);
    float v = (z[i] - mean[gb*1024 + c]) * rstd[gb*1024 + c];
    z[i] = fmaxf(v, 0.f);
}

__global__ void bins_k(float* __restrict__ cp, const float* __restrict__ alpha_p) {
    int i = blockIdx.x*256 + threadIdx.x;
    if (i >= BB*NP1) return;
    float a = *alpha_p;
    int b = i / NP1, r = i % NP1;
    float* base = cp + (size_t)b*CPS;
    base[(size_t)r*NP1 + 1024] = a;
    base[(size_t)1024*NP1 + r] = a;
}

__global__ void erow_k(const float* __restrict__ cp, float* __restrict__ er,
                       float* __restrict__ rm) {
    int i = blockIdx.x, b = blockIdx.y;
    const float* row = cp + (size_t)b*CPS + (size_t)i*NP1;
    float m = -1e30f;
    for (int j = threadIdx.x; j < NP1; j += 256) m = fmaxf(m, row[j]);
    __shared__ float sh[256];
    m = bmax256(m, sh);
    float* e = er + (size_t)b*CPS + (size_t)i*NP1;
    for (int j = threadIdx.x; j < NP1; j += 256) e[j] = __expf(row[j] - m);
    if (threadIdx.x == 0) rm[b*NP1 + i] = m;
}

__global__ void cmax_k(const float* __restrict__ cp, float* __restrict__ cm) {
    int j = blockIdx.x*256 + threadIdx.x, b = blockIdx.y;
    if (j >= NP1) return;
    const float* base = cp + (size_t)b*CPS + j;
    float m = -1e30f;
    for (int i = 0; i < NP1; i++) m = fmaxf(m, base[(size_t)i*NP1]);
    cm[b*NP1 + j] = m;
}

__global__ void texp_k(const float* __restrict__ cp, const float* __restrict__ cm,
                       float* __restrict__ ect) {
    __shared__ float t[32][33];
    int b = blockIdx.z;
    int i0 = blockIdx.y*32, j0 = blockIdx.x*32;
    int i = i0 + threadIdx.y, j = j0 + threadIdx.x;
    if (i < NP1 && j < NP1)
        t[threadIdx.y][threadIdx.x] = cp[(size_t)b*CPS + (size_t)i*NP1 + j];
    __syncthreads();
    int jo = j0 + threadIdx.y, io = i0 + threadIdx.x;
    if (jo < NP1 && io < NP1)
        ect[(size_t)b*CPS + (size_t)jo*NP1 + io] = __expf(t[threadIdx.x][threadIdx.y] - cm[b*NP1 + jo]);
}

__global__ void initev_k(float* __restrict__ ev) {
    int i = blockIdx.x*256 + threadIdx.x;
    if (i < BB*NP1) ev[i] = 1.f;
}

__global__ void iter_k(const float* __restrict__ E, const float* __restrict__ evin,
                       const float* __restrict__ mx, float* __restrict__ lg,
                       float* __restrict__ ex) {
    int i = blockIdx.x, b = blockIdx.y;
    const float* row = E + (size_t)b*CPS + (size_t)i*NP1;
    const float* ev = evin + b*NP1;
    float s = 0.f;
    for (int j = threadIdx.x; j < NP1; j += 256) s += row[j]*ev[j];
    __shared__ float sh[256];
    s = bsum256(s, sh);
    if (threadIdx.x == 0) {
        float lmu = (i < NN) ? NORMC : (LOGNC + NORMC);
        float o = lmu - (mx[b*NP1 + i] + logf(s));
        lg[b*NP1 + i] = o;
        ex[b*NP1 + i] = expf(o);
    }
}

__global__ void out_k(const float* __restrict__ cp, const float* __restrict__ u,
                      const float* __restrict__ v, float* __restrict__ out) {
    size_t idx = (size_t)blockIdx.x*256 + threadIdx.x;
    if (idx >= (size_t)BB*CPS) return;
    int b = (int)(idx / CPS);
    int r = (int)(idx % CPS);
    int i = r / NP1, j = r % NP1;
    out[idx] = cp[idx] + u[b*NP1 + i] + v[b*NP1 + j] - NORMC;
}

// ---------------- host wrappers ----------------
static void GT(const float* A, const float* B, const float* bias, const float* Res,
               float* C, int M, int N, int K, int lda, int ldb, int ldc,
               int nz, int NH, ll sAb, ll sAh, ll sBb, ll sBh, ll sCb, ll sCh,
               float alpha) {
    dim3 g(N/128, M/128, nz);
    gemm_k<128,128,16,8,8,true><<<g,256>>>(A,B,bias,Res,C,M,N,K,lda,ldb,ldc,
                                           NH,sAb,sAh,sBb,sBh,sCb,sCh,alpha);
}
static void GNF(const float* A, const float* B, float* C, int M, int N, int K,
                int lda, int ldb, int ldc, int nz, int NH,
                ll sAb, ll sAh, ll sBb, ll sBh, ll sCb, ll sCh) {
    dim3 g(N/64, M/128, nz);
    gemm_k<128,64,16,8,4,false><<<g,256>>>(A,B,nullptr,nullptr,C,M,N,K,lda,ldb,ldc,
                                           NH,sAb,sAh,sBb,sBh,sCb,sCh,1.f);
}

extern "C" void kernel_launch(void* const* d_in, const int* in_sizes, int n_in,
                              void* d_out, int out_size) {
    (void)in_sizes; (void)n_in; (void)out_size;
    float* P = nullptr;
    cudaGetSymbolAddress((void**)&P, g_pool);

    const float* descs0 = (const float*)d_in[0];
    const float* descs1 = (const float*)d_in[1];
    const float* Wq = (const float*)d_in[2];  const float* bq = (const float*)d_in[3];
    const float* Wk = (const float*)d_in[4];  const float* bk = (const float*)d_in[5];
    const float* Wv = (const float*)d_in[6];  const float* bv = (const float*)d_in[7];
    const float* Wm = (const float*)d_in[8];  const float* bm = (const float*)d_in[9];
    const float* W1 = (const float*)d_in[10]; const float* b1 = (const float*)d_in[11];
    const float* W2 = (const float*)d_in[12]; const float* b2 = (const float*)d_in[13];
    const float* Wf = (const float*)d_in[14]; const float* bf = (const float*)d_in[15];
    const float* bscore = (const float*)d_in[16];
    float* out = (float*)d_out;

    float* X   = P + O_X;
    float* Qb  = P + O_Q;
    float* Kb  = P + O_K;
    float* Vb  = P + O_V;
    float* Sb  = P + O_S;
    float* AO  = P + O_AO;
    float* CAT = P + O_CAT;
    float* Zb  = P + O_Z;
    float* MEAN= P + O_MEAN;
    float* RSTD= P + O_RSTD;
    float* WMP = P + O_WMP;
    float* CP  = P + O_CP;
    float* ER  = P + O_ER;
    float* EC  = P + O_EC;
    float* RM  = P + O_RM;
    float* CM  = P + O_CM;
    float* U   = P + O_U;
    float* VV  = P + O_VV;
    float* EU  = P + O_EU;
    float* EV  = P + O_EV;

    // init: x0|x1 node-major (inputs are already [B,N,D])
    cudaMemcpyAsync(X,        descs0, XSZ*sizeof(float), cudaMemcpyDeviceToDevice);
    cudaMemcpyAsync(X + XSZ,  descs1, XSZ*sizeof(float), cudaMemcpyDeviceToDevice);
    perm_k<<<(LL*DD*DD+255)/256, 256>>>(Wm, WMP);

    const ll sBN = (ll)NN*DD;   // per-batch stride in Q/K/V/X (node-major)
    for (int l = 0; l < LL; l++) {
        bool cross = (l & 1);
        const float* wq = Wq + (size_t)l*DD*DD;
        const float* wk = Wk + (size_t)l*DD*DD;
        const float* wv = Wv + (size_t)l*DD*DD;
        const float* wmp= WMP+ (size_t)l*DD*DD;
        const float* w1 = W1 + (size_t)l*2*DD*2*DD;
        const float* w2 = W2 + (size_t)l*DD*2*DD;

        // projections for BOTH graphs from pre-update X
        GT(X, wq, bq + l*DD, nullptr, Qb, 8192, 512, 512, 512,512,512, 1,1, 0,0,0,0,0,0, 1.f);
        GT(X, wk, bk + l*DD, nullptr, Kb, 8192, 512, 512, 512,512,512, 1,1, 0,0,0,0,0,0, 1.f);
        GT(X, wv, bv + l*DD, nullptr, Vb, 8192, 512, 512, 512,512,512, 1,1, 0,0,0,0,0,0, 1.f);

        for (int g = 0; g < 2; g++) {
            int sg = cross ? 1-g : g;
            const float* Qg = Qb + (size_t)g*XSZ;
            const float* Kg = Kb + (size_t)sg*XSZ;
            const float* Vg = Vb + (size_t)sg*XSZ;
            // scores[b,h,n,m] = Q·K / 8
            GT(Qg, Kg, nullptr, nullptr, Sb, 1024,1024,64, 512,512,1024,
               BB*HH, HH, sBN, 64, sBN, 64, (ll)HH*NN*NN, (ll)NN*NN, 0.125f);
            softmax_k<<<BB*HH*NN, 256>>>(Sb);
            // AO[b,n,h*64+hd] = P·V
            GNF(Sb, Vg, AO + (size_t)g*XSZ, 1024,64,1024, 1024,512,512,
                BB*HH, HH, (ll)HH*NN*NN, (ll)NN*NN, sBN, 64, sBN, 64);
        }
        // msg into CAT[:,512:1024]
        GT(AO, wmp, bm + l*DD, nullptr, CAT + 512, 8192,512,512, 512,512,1024,
           1,1, 0,0,0,0,0,0, 1.f);
        cat_copy_k<<<(int)((2*XSZ+255)/256), 256>>>(X, CAT);
        // z = CAT @ W1^T + b1
        GT(CAT, w1, b1 + l*2*DD, nullptr, Zb, 8192,1024,1024, 1024,1024,1024,
           1,1, 0,0,0,0,0,0, 1.f);
        in_stats_k<<<dim3(32, 8), 256>>>(Zb, MEAN, RSTD);
        in_apply_k<<<(int)(((size_t)2*BB*NN*1024 + 255)/256), 256>>>(Zb, MEAN, RSTD);
        // X += Z @ W2^T + b2
        GT(Zb, w2, b2 + l*DD, X, X, 8192,512,1024, 1024,1024,512,
           1,1, 0,0,0,0,0,0, 1.f);
    }

    // final projection (m0|m1 into Qb)
    GT(X, Wf, bf, nullptr, Qb, 8192,512,512, 512,512,512, 1,1, 0,0,0,0,0,0, 1.f);
    // scores -> couplings interior (ldc = 1025)
    GT(Qb, Qb + XSZ, nullptr, nullptr, CP, 1024,1024,512, 512,512,NP1,
       BB, 1, sBN, 0, sBN, 0, (ll)CPS, 0, 0.044194173824159216f);
    bins_k<<<(BB*NP1+255)/256, 256>>>(CP, bscore);

    // Sinkhorn: precompute stabilized exponentials once
    erow_k<<<dim3(NP1, BB), 256>>>(CP, ER, RM);
    cmax_k<<<dim3((NP1+255)/256, BB), 256>>>(CP, CM);
    texp_k<<<dim3(33, 33, BB), dim3(32, 32)>>>(CP, CM, EC);
    initev_k<<<(BB*NP1+255)/256, 256>>>(EV);
    for (int it = 0; it < 100; it++) {
        iter_k<<<dim3(NP1, BB), 256>>>(ER, EV, RM, U, EU);   // u-update
        iter_k<<<dim3(NP1, BB), 256>>>(EC, EU, CM, VV, EV);  // v-update
    }
    out_k<<<(int)(((size_t)BB*CPS + 255)/256), 256>>>(CP, U, VV, out);
}